// round 1
// baseline (speedup 1.0000x reference)
#include <cuda_runtime.h>
#include <math_constants.h>

// Problem constants (fixed by the dataset: x [4,2048,1024], W [1024,1024])
#define BATCH   4
#define SEQ     2048
#define DMODEL  1024
#define MROWS   (BATCH * SEQ)          // 8192
#define INV_SQRT_DHEAD 0.125f          // 1/sqrt(64)

// -------- scratch (static __device__: allocation-free per harness rules) ----
__device__ float g_Q [MROWS * DMODEL];                  // 32 MB
__device__ float g_K [MROWS * DMODEL];                  // 32 MB
__device__ float g_V [MROWS * DMODEL];                  // 32 MB
__device__ float g_AO[MROWS * DMODEL];                  // 32 MB
__device__ float g_P [(size_t)BATCH * SEQ * SEQ];       // 64 MB (scores -> weights)

// ============================================================================
// 128x128x8 SGEMM, 256 threads, 8x8 micro-tile per thread.
//   C[M,N] = scale * (A[M,K] @ op(B)) (+ bias[n])
//   TRANS_B=false: B is [K,N] row-major.   TRANS_B=true: B is [N,K] row-major.
//   CAUSAL_SKIP: skip 128x128 tiles strictly above the diagonal (bn > bm).
//   Batched via blockIdx.z with element strides sA/sB/sC.
// Requires M%128==0, N%128==0, K%8==0 (true for all shapes here).
// ============================================================================
template<bool TRANS_B, bool HAS_BIAS, bool CAUSAL_SKIP>
__global__ __launch_bounds__(256, 2)
void sgemm_kernel(const float* __restrict__ A, const float* __restrict__ Bm,
                  const float* __restrict__ bias, float* __restrict__ C,
                  int M, int N, int K, float scale,
                  size_t sA, size_t sB, size_t sC)
{
    const int bm = blockIdx.y;
    const int bn = blockIdx.x;
    if (CAUSAL_SKIP && bn > bm) return;

    const int z = blockIdx.z;
    A  += (size_t)z * sA;
    Bm += (size_t)z * sB;
    C  += (size_t)z * sC;

    __shared__ float As[8][128];
    __shared__ float Bs[8][128];

    const int tid = threadIdx.x;
    const int tx  = tid & 15;   // column group (8 cols each)
    const int ty  = tid >> 4;   // row group (8 rows each)

    const int m0 = bm * 128;
    const int n0 = bn * 128;

    // A-tile (and transposed B-tile) loader: 128 rows x 8 cols, float4 each.
    const int la_row = tid >> 1;          // 0..127
    const int la_col = (tid & 1) * 4;     // 0 or 4
    // B-tile (nn) loader: 8 rows x 128 cols.
    const int lb_row = tid >> 5;          // 0..7
    const int lb_col = (tid & 31) * 4;    // 0..124

    float acc[8][8];
    #pragma unroll
    for (int i = 0; i < 8; i++)
        #pragma unroll
        for (int j = 0; j < 8; j++) acc[i][j] = 0.f;

    for (int k0 = 0; k0 < K; k0 += 8) {
        // ---- load A tile (transpose into As[k][m]) ----
        {
            float4 av = *reinterpret_cast<const float4*>(
                A + (size_t)(m0 + la_row) * K + (k0 + la_col));
            As[la_col + 0][la_row] = av.x;
            As[la_col + 1][la_row] = av.y;
            As[la_col + 2][la_row] = av.z;
            As[la_col + 3][la_row] = av.w;
        }
        // ---- load B tile ----
        if (!TRANS_B) {
            float4 bv = *reinterpret_cast<const float4*>(
                Bm + (size_t)(k0 + lb_row) * N + (n0 + lb_col));
            *reinterpret_cast<float4*>(&Bs[lb_row][lb_col]) = bv;
        } else {
            // Bm is [N,K] row-major: Bs[kk][n] = Bm[n0+n][k0+kk]
            float4 bv = *reinterpret_cast<const float4*>(
                Bm + (size_t)(n0 + la_row) * K + (k0 + la_col));
            Bs[la_col + 0][la_row] = bv.x;
            Bs[la_col + 1][la_row] = bv.y;
            Bs[la_col + 2][la_row] = bv.z;
            Bs[la_col + 3][la_row] = bv.w;
        }
        __syncthreads();

        #pragma unroll
        for (int kk = 0; kk < 8; kk++) {
            float4 a0 = *reinterpret_cast<const float4*>(&As[kk][ty * 8 + 0]);
            float4 a1 = *reinterpret_cast<const float4*>(&As[kk][ty * 8 + 4]);
            float4 b0 = *reinterpret_cast<const float4*>(&Bs[kk][tx * 8 + 0]);
            float4 b1 = *reinterpret_cast<const float4*>(&Bs[kk][tx * 8 + 4]);
            const float af[8] = {a0.x, a0.y, a0.z, a0.w, a1.x, a1.y, a1.z, a1.w};
            const float bf[8] = {b0.x, b0.y, b0.z, b0.w, b1.x, b1.y, b1.z, b1.w};
            #pragma unroll
            for (int i = 0; i < 8; i++)
                #pragma unroll
                for (int j = 0; j < 8; j++)
                    acc[i][j] = fmaf(af[i], bf[j], acc[i][j]);
        }
        __syncthreads();
    }

    // ---- epilogue: scale, bias, vectorized store ----
    #pragma unroll
    for (int i = 0; i < 8; i++) {
        const int r = m0 + ty * 8 + i;
        #pragma unroll
        for (int j = 0; j < 8; j += 4) {
            const int c = n0 + tx * 8 + j;
            float4 v;
            v.x = acc[i][j + 0] * scale;
            v.y = acc[i][j + 1] * scale;
            v.z = acc[i][j + 2] * scale;
            v.w = acc[i][j + 3] * scale;
            if (HAS_BIAS) {
                v.x += bias[c + 0];
                v.y += bias[c + 1];
                v.z += bias[c + 2];
                v.w += bias[c + 3];
            }
            *reinterpret_cast<float4*>(C + (size_t)r * N + c) = v;
        }
    }
}

// ============================================================================
// Causal row softmax on scores, in-place -> weights.
// One block per (b,q) row. Valid keys: k in [0, q]. Writes 0 for k > q so the
// downstream P@V GEMM can run dense over K=SEQ.
// ============================================================================
__global__ __launch_bounds__(256)
void softmax_causal_kernel(float* __restrict__ P)
{
    const int row = blockIdx.x;          // 0 .. BATCH*SEQ-1
    const int b = row / SEQ;
    const int q = row % SEQ;
    float* p = P + (size_t)b * SEQ * SEQ + (size_t)q * SEQ;
    const int n = q + 1;

    __shared__ float red[256];
    const int tid = threadIdx.x;

    // --- max ---
    float mx = -CUDART_INF_F;
    for (int k = tid; k < n; k += 256) mx = fmaxf(mx, p[k]);
    red[tid] = mx; __syncthreads();
    #pragma unroll
    for (int s = 128; s > 0; s >>= 1) {
        if (tid < s) red[tid] = fmaxf(red[tid], red[tid + s]);
        __syncthreads();
    }
    mx = red[0]; __syncthreads();

    // --- exp + sum (write exp in place) ---
    float sum = 0.f;
    for (int k = tid; k < n; k += 256) {
        float e = expf(p[k] - mx);
        p[k] = e;
        sum += e;
    }
    red[tid] = sum; __syncthreads();
    #pragma unroll
    for (int s = 128; s > 0; s >>= 1) {
        if (tid < s) red[tid] += red[tid + s];
        __syncthreads();
    }
    const float inv = 1.f / red[0];

    // --- normalize + zero the masked tail ---
    for (int k = tid; k < n; k += 256) p[k] *= inv;
    for (int k = n + tid; k < SEQ; k += 256) p[k] = 0.f;
}

// ============================================================================
extern "C" void kernel_launch(void* const* d_in, const int* /*in_sizes*/, int /*n_in*/,
                              void* d_out, int /*out_size*/)
{
    const float* x  = (const float*)d_in[0];
    const float* Wq = (const float*)d_in[1];
    const float* bq = (const float*)d_in[2];
    const float* Wk = (const float*)d_in[3];
    const float* bk = (const float*)d_in[4];
    const float* Wv = (const float*)d_in[5];
    const float* bv = (const float*)d_in[6];
    const float* Wo = (const float*)d_in[7];
    const float* bo = (const float*)d_in[8];
    float* out = (float*)d_out;

    float *Q, *K, *V, *AO, *P;
    cudaGetSymbolAddress((void**)&Q,  g_Q);
    cudaGetSymbolAddress((void**)&K,  g_K);
    cudaGetSymbolAddress((void**)&V,  g_V);
    cudaGetSymbolAddress((void**)&AO, g_AO);
    cudaGetSymbolAddress((void**)&P,  g_P);

    const dim3 blk(256);

    // 1) Q/K/V projections: [8192,1024] @ [1024,1024] + b
    {
        dim3 grid(DMODEL / 128, MROWS / 128, 1);
        sgemm_kernel<false, true, false><<<grid, blk>>>(
            x, Wq, bq, Q, MROWS, DMODEL, DMODEL, 1.f, 0, 0, 0);
        sgemm_kernel<false, true, false><<<grid, blk>>>(
            x, Wk, bk, K, MROWS, DMODEL, DMODEL, 1.f, 0, 0, 0);
        sgemm_kernel<false, true, false><<<grid, blk>>>(
            x, Wv, bv, V, MROWS, DMODEL, DMODEL, 1.f, 0, 0, 0);
    }

    // 2) scores = Q @ K^T / 8 (batched, causal tile skip)
    {
        dim3 grid(SEQ / 128, SEQ / 128, BATCH);
        sgemm_kernel<true, false, true><<<grid, blk>>>(
            Q, K, nullptr, P, SEQ, SEQ, DMODEL, INV_SQRT_DHEAD,
            (size_t)SEQ * DMODEL, (size_t)SEQ * DMODEL, (size_t)SEQ * SEQ);
    }

    // 3) causal softmax (in place on P)
    softmax_causal_kernel<<<MROWS, blk>>>(P);

    // 4) attn_out = P @ V (batched dense; masked weights are exact zeros)
    {
        dim3 grid(DMODEL / 128, SEQ / 128, BATCH);
        sgemm_kernel<false, false, false><<<grid, blk>>>(
            P, V, nullptr, AO, SEQ, DMODEL, SEQ, 1.f,
            (size_t)SEQ * SEQ, (size_t)SEQ * DMODEL, (size_t)SEQ * DMODEL);
    }

    // 5) out = attn_out @ Wo + bo
    {
        dim3 grid(DMODEL / 128, MROWS / 128, 1);
        sgemm_kernel<false, true, false><<<grid, blk>>>(
            AO, Wo, bo, out, MROWS, DMODEL, DMODEL, 1.f, 0, 0, 0);
    }
}

// round 2
// speedup vs baseline: 1.0005x; 1.0005x over previous
#include <cuda_runtime.h>
#include <math_constants.h>

// Problem constants (fixed by the dataset: x [4,2048,1024], W [1024,1024])
#define BATCH   4
#define SEQ     2048
#define DMODEL  1024
#define MROWS   (BATCH * SEQ)          // 8192
#define INV_SQRT_DHEAD 0.125f          // 1/sqrt(64)

// -------- scratch (static __device__: allocation-free per harness rules) ----
__device__ float g_Q [MROWS * DMODEL];                  // 32 MB
__device__ float g_K [MROWS * DMODEL];                  // 32 MB
__device__ float g_V [MROWS * DMODEL];                  // 32 MB
__device__ float g_AO[MROWS * DMODEL];                  // 32 MB
__device__ float g_P [(size_t)BATCH * SEQ * SEQ];       // 64 MB (scores -> weights)

// ============================================================================
// 128x128x8 SGEMM, 256 threads, 8x8 micro-tile per thread.
//   C[M,N] = scale * (A[M,K] @ op(B)) (+ bias[n])
//   TRANS_B=false: B is [K,N] row-major.   TRANS_B=true: B is [N,K] row-major.
//   CAUSAL_SKIP: skip 128x128 tiles strictly above the diagonal (bn > bm).
//   Batched via blockIdx.z with element strides sA/sB/sC.
// Requires M%128==0, N%128==0, K%8==0 (true for all shapes here).
// ============================================================================
template<bool TRANS_B, bool HAS_BIAS, bool CAUSAL_SKIP>
__global__ __launch_bounds__(256, 2)
void sgemm_kernel(const float* __restrict__ A, const float* __restrict__ Bm,
                  const float* __restrict__ bias, float* __restrict__ C,
                  int M, int N, int K, float scale,
                  size_t sA, size_t sB, size_t sC)
{
    const int bm = blockIdx.y;
    const int bn = blockIdx.x;
    if (CAUSAL_SKIP && bn > bm) return;

    const int z = blockIdx.z;
    A  += (size_t)z * sA;
    Bm += (size_t)z * sB;
    C  += (size_t)z * sC;

    __shared__ float As[8][128];
    __shared__ float Bs[8][128];

    const int tid = threadIdx.x;
    const int tx  = tid & 15;   // column group (8 cols each)
    const int ty  = tid >> 4;   // row group (8 rows each)

    const int m0 = bm * 128;
    const int n0 = bn * 128;

    // A-tile (and transposed B-tile) loader: 128 rows x 8 cols, float4 each.
    const int la_row = tid >> 1;          // 0..127
    const int la_col = (tid & 1) * 4;     // 0 or 4
    // B-tile (nn) loader: 8 rows x 128 cols.
    const int lb_row = tid >> 5;          // 0..7
    const int lb_col = (tid & 31) * 4;    // 0..124

    float acc[8][8];
    #pragma unroll
    for (int i = 0; i < 8; i++)
        #pragma unroll
        for (int j = 0; j < 8; j++) acc[i][j] = 0.f;

    for (int k0 = 0; k0 < K; k0 += 8) {
        // ---- load A tile (transpose into As[k][m]) ----
        {
            float4 av = *reinterpret_cast<const float4*>(
                A + (size_t)(m0 + la_row) * K + (k0 + la_col));
            As[la_col + 0][la_row] = av.x;
            As[la_col + 1][la_row] = av.y;
            As[la_col + 2][la_row] = av.z;
            As[la_col + 3][la_row] = av.w;
        }
        // ---- load B tile ----
        if (!TRANS_B) {
            float4 bv = *reinterpret_cast<const float4*>(
                Bm + (size_t)(k0 + lb_row) * N + (n0 + lb_col));
            *reinterpret_cast<float4*>(&Bs[lb_row][lb_col]) = bv;
        } else {
            // Bm is [N,K] row-major: Bs[kk][n] = Bm[n0+n][k0+kk]
            float4 bv = *reinterpret_cast<const float4*>(
                Bm + (size_t)(n0 + la_row) * K + (k0 + la_col));
            Bs[la_col + 0][la_row] = bv.x;
            Bs[la_col + 1][la_row] = bv.y;
            Bs[la_col + 2][la_row] = bv.z;
            Bs[la_col + 3][la_row] = bv.w;
        }
        __syncthreads();

        #pragma unroll
        for (int kk = 0; kk < 8; kk++) {
            float4 a0 = *reinterpret_cast<const float4*>(&As[kk][ty * 8 + 0]);
            float4 a1 = *reinterpret_cast<const float4*>(&As[kk][ty * 8 + 4]);
            float4 b0 = *reinterpret_cast<const float4*>(&Bs[kk][tx * 8 + 0]);
            float4 b1 = *reinterpret_cast<const float4*>(&Bs[kk][tx * 8 + 4]);
            const float af[8] = {a0.x, a0.y, a0.z, a0.w, a1.x, a1.y, a1.z, a1.w};
            const float bf[8] = {b0.x, b0.y, b0.z, b0.w, b1.x, b1.y, b1.z, b1.w};
            #pragma unroll
            for (int i = 0; i < 8; i++)
                #pragma unroll
                for (int j = 0; j < 8; j++)
                    acc[i][j] = fmaf(af[i], bf[j], acc[i][j]);
        }
        __syncthreads();
    }

    // ---- epilogue: scale, bias, vectorized store ----
    #pragma unroll
    for (int i = 0; i < 8; i++) {
        const int r = m0 + ty * 8 + i;
        #pragma unroll
        for (int j = 0; j < 8; j += 4) {
            const int c = n0 + tx * 8 + j;
            float4 v;
            v.x = acc[i][j + 0] * scale;
            v.y = acc[i][j + 1] * scale;
            v.z = acc[i][j + 2] * scale;
            v.w = acc[i][j + 3] * scale;
            if (HAS_BIAS) {
                v.x += bias[c + 0];
                v.y += bias[c + 1];
                v.z += bias[c + 2];
                v.w += bias[c + 3];
            }
            *reinterpret_cast<float4*>(C + (size_t)r * N + c) = v;
        }
    }
}

// ============================================================================
// Causal row softmax on scores, in-place -> weights.
// One block per (b,q) row. Valid keys: k in [0, q]. Writes 0 for k > q so the
// downstream P@V GEMM can run dense over K=SEQ.
// ============================================================================
__global__ __launch_bounds__(256)
void softmax_causal_kernel(float* __restrict__ P)
{
    const int row = blockIdx.x;          // 0 .. BATCH*SEQ-1
    const int b = row / SEQ;
    const int q = row % SEQ;
    float* p = P + (size_t)b * SEQ * SEQ + (size_t)q * SEQ;
    const int n = q + 1;

    __shared__ float red[256];
    const int tid = threadIdx.x;

    // --- max ---
    float mx = -CUDART_INF_F;
    for (int k = tid; k < n; k += 256) mx = fmaxf(mx, p[k]);
    red[tid] = mx; __syncthreads();
    #pragma unroll
    for (int s = 128; s > 0; s >>= 1) {
        if (tid < s) red[tid] = fmaxf(red[tid], red[tid + s]);
        __syncthreads();
    }
    mx = red[0]; __syncthreads();

    // --- exp + sum (write exp in place) ---
    float sum = 0.f;
    for (int k = tid; k < n; k += 256) {
        float e = expf(p[k] - mx);
        p[k] = e;
        sum += e;
    }
    red[tid] = sum; __syncthreads();
    #pragma unroll
    for (int s = 128; s > 0; s >>= 1) {
        if (tid < s) red[tid] += red[tid + s];
        __syncthreads();
    }
    const float inv = 1.f / red[0];

    // --- normalize + zero the masked tail ---
    for (int k = tid; k < n; k += 256) p[k] *= inv;
    for (int k = n + tid; k < SEQ; k += 256) p[k] = 0.f;
}

// ============================================================================
extern "C" void kernel_launch(void* const* d_in, const int* /*in_sizes*/, int /*n_in*/,
                              void* d_out, int /*out_size*/)
{
    const float* x  = (const float*)d_in[0];
    const float* Wq = (const float*)d_in[1];
    const float* bq = (const float*)d_in[2];
    const float* Wk = (const float*)d_in[3];
    const float* bk = (const float*)d_in[4];
    const float* Wv = (const float*)d_in[5];
    const float* bv = (const float*)d_in[6];
    const float* Wo = (const float*)d_in[7];
    const float* bo = (const float*)d_in[8];
    float* out = (float*)d_out;

    float *Q, *K, *V, *AO, *P;
    cudaGetSymbolAddress((void**)&Q,  g_Q);
    cudaGetSymbolAddress((void**)&K,  g_K);
    cudaGetSymbolAddress((void**)&V,  g_V);
    cudaGetSymbolAddress((void**)&AO, g_AO);
    cudaGetSymbolAddress((void**)&P,  g_P);

    const dim3 blk(256);

    // 1) Q/K/V projections: [8192,1024] @ [1024,1024] + b
    {
        dim3 grid(DMODEL / 128, MROWS / 128, 1);
        sgemm_kernel<false, true, false><<<grid, blk>>>(
            x, Wq, bq, Q, MROWS, DMODEL, DMODEL, 1.f, 0, 0, 0);
        sgemm_kernel<false, true, false><<<grid, blk>>>(
            x, Wk, bk, K, MROWS, DMODEL, DMODEL, 1.f, 0, 0, 0);
        sgemm_kernel<false, true, false><<<grid, blk>>>(
            x, Wv, bv, V, MROWS, DMODEL, DMODEL, 1.f, 0, 0, 0);
    }

    // 2) scores = Q @ K^T / 8 (batched, causal tile skip)
    {
        dim3 grid(SEQ / 128, SEQ / 128, BATCH);
        sgemm_kernel<true, false, true><<<grid, blk>>>(
            Q, K, nullptr, P, SEQ, SEQ, DMODEL, INV_SQRT_DHEAD,
            (size_t)SEQ * DMODEL, (size_t)SEQ * DMODEL, (size_t)SEQ * SEQ);
    }

    // 3) causal softmax (in place on P)
    softmax_causal_kernel<<<MROWS, blk>>>(P);

    // 4) attn_out = P @ V (batched dense; masked weights are exact zeros)
    {
        dim3 grid(DMODEL / 128, SEQ / 128, BATCH);
        sgemm_kernel<false, false, false><<<grid, blk>>>(
            P, V, nullptr, AO, SEQ, DMODEL, SEQ, 1.f,
            (size_t)SEQ * SEQ, (size_t)SEQ * DMODEL, (size_t)SEQ * DMODEL);
    }

    // 5) out = attn_out @ Wo + bo
    {
        dim3 grid(DMODEL / 128, MROWS / 128, 1);
        sgemm_kernel<false, true, false><<<grid, blk>>>(
            AO, Wo, bo, out, MROWS, DMODEL, DMODEL, 1.f, 0, 0, 0);
    }
}

// round 4
// speedup vs baseline: 2.4646x; 2.4634x over previous
#include <cuda_runtime.h>
#include <cuda_bf16.h>
#include <math_constants.h>
#include <stdint.h>

#define BATCH 4
#define SEQ   2048
#define DM    1024
#define MROWS (BATCH * SEQ)

// ---- GEMM tiling ----------------------------------------------------------
#define TM 128
#define TN 128
#define BK 64                         // bf16 elems per K-chunk (128 bytes/row)
#define TILE_BYTES (128 * 128)        // 16 KB per operand tile
#define STAGE_BYTES (4 * TILE_BYTES)  // Ahi,Alo,Bhi,Blo = 64 KB
#define NSTAGE 3
#define SMEM_DYN (NSTAGE * STAGE_BYTES)   // 192 KB

typedef __nv_bfloat16 bf16;

// ---- scratch (static __device__: allocation-free) --------------------------
#define AL1K __align__(1024)
__device__ AL1K bf16  g_xh [MROWS * DM];
__device__ AL1K bf16  g_xl [MROWS * DM];
__device__ AL1K bf16  g_wqh[DM * DM];
__device__ AL1K bf16  g_wql[DM * DM];
__device__ AL1K bf16  g_wkh[DM * DM];
__device__ AL1K bf16  g_wkl[DM * DM];
__device__ AL1K bf16  g_wvh[DM * DM];
__device__ AL1K bf16  g_wvl[DM * DM];
__device__ AL1K bf16  g_woh[DM * DM];
__device__ AL1K bf16  g_wol[DM * DM];
__device__ AL1K bf16  g_qh [MROWS * DM];
__device__ AL1K bf16  g_ql [MROWS * DM];
__device__ AL1K bf16  g_kh [MROWS * DM];
__device__ AL1K bf16  g_kl [MROWS * DM];
__device__ AL1K float g_v  [MROWS * DM];
__device__ AL1K bf16  g_vth[MROWS * DM];   // [B][D][S]
__device__ AL1K bf16  g_vtl[MROWS * DM];
__device__ AL1K float g_p  [(size_t)BATCH * SEQ * SEQ];
__device__ AL1K bf16  g_ph [(size_t)BATCH * SEQ * SEQ];
__device__ AL1K bf16  g_pl [(size_t)BATCH * SEQ * SEQ];
__device__ AL1K bf16  g_aoh[MROWS * DM];
__device__ AL1K bf16  g_aol[MROWS * DM];

// ---- PTX helpers (all plain sm_80-era: valid on target sm_103) -------------
__device__ __forceinline__ uint32_t s2u(const void* p) {
    uint32_t a;
    asm("{ .reg .u64 t; cvta.to.shared.u64 t, %1; cvt.u32.u64 %0, t; }" : "=r"(a) : "l"(p));
    return a;
}
__device__ __forceinline__ void cp16(uint32_t saddr, const void* gaddr) {
    asm volatile("cp.async.cg.shared.global [%0], [%1], 16;" :: "r"(saddr), "l"(gaddr));
}
__device__ __forceinline__ void cp_commit() { asm volatile("cp.async.commit_group;"); }
__device__ __forceinline__ void cp_wait2()  { asm volatile("cp.async.wait_group 2;" ::: "memory"); }

__device__ __forceinline__ void ldm4(uint32_t* r, uint32_t addr) {
    asm volatile("ldmatrix.sync.aligned.m8n8.x4.shared.b16 {%0,%1,%2,%3}, [%4];"
                 : "=r"(r[0]), "=r"(r[1]), "=r"(r[2]), "=r"(r[3]) : "r"(addr));
}
__device__ __forceinline__ void mma16816(float* c, const uint32_t* a, const uint32_t* b) {
    asm volatile(
        "mma.sync.aligned.m16n8k16.row.col.f32.bf16.bf16.f32 "
        "{%0,%1,%2,%3}, {%4,%5,%6,%7}, {%8,%9}, {%0,%1,%2,%3};"
        : "+f"(c[0]), "+f"(c[1]), "+f"(c[2]), "+f"(c[3])
        : "r"(a[0]), "r"(a[1]), "r"(a[2]), "r"(a[3]), "r"(b[0]), "r"(b[1]));
}
__device__ __forceinline__ uint32_t pk2(float a, float b) {
    __nv_bfloat162 t = __floats2bfloat162_rn(a, b);
    return *reinterpret_cast<uint32_t*>(&t);
}

// ============================================================================
// Tensor-core GEMM: C[M,N] = scale*((Ahi+Alo)[M,K] @ ((Bhi+Blo)[N,K])^T)+bias
//   3-term split product: Ahi*Bhi + Ahi*Blo + Alo*Bhi (fp32 accum).
//   OUTMODE 0: fp32 out (Cf).  OUTMODE 1: bf16 split out (Ch, Cl).
//   CAUSAL: skip 128x128 tiles strictly above diagonal.
//   PVLIM : K truncated at causal boundary (nchunk = (m0+128)/64).
// ============================================================================
template<int OUTMODE, bool HAS_BIAS, bool CAUSAL, bool PVLIM>
__global__ __launch_bounds__(256, 1)
void tc_gemm(const bf16* __restrict__ Ah, const bf16* __restrict__ Al,
             const bf16* __restrict__ Bh, const bf16* __restrict__ Bl,
             const float* __restrict__ bias,
             float* __restrict__ Cf, bf16* __restrict__ Ch, bf16* __restrict__ Cl,
             int Kfull, int ldA, int ldB, int ldC, float scale,
             size_t sA, size_t sB, size_t sC)
{
    const int m0 = blockIdx.y * TM;
    const int n0 = blockIdx.x * TN;
    if (CAUSAL && n0 > m0) return;

    const int z = blockIdx.z;
    Ah += (size_t)z * sA;  Al += (size_t)z * sA;
    Bh += (size_t)z * sB;  Bl += (size_t)z * sB;

    extern __shared__ char dsm[];
    const uint32_t smem = s2u(dsm);

    const int tid  = threadIdx.x;
    const int wid  = tid >> 5;
    const int lane = tid & 31;
    const int wm   = wid & 3;    // 4 warp-rows  (32 M-rows each)
    const int wn   = wid >> 2;   // 2 warp-cols  (64 N-cols each)

    const int nchunk = PVLIM ? (m0 + TM) / BK : Kfull / BK;

    // ---- loader setup: each thread = half a row (4x16B segs) of each tile --
    const int lrow = tid >> 1;            // 0..127
    const int sb   = (tid & 1) * 4;       // seg base 0 or 4
    const char* gp[4];
    uint32_t    so[4][4];
    {
        const bf16* bases[4] = {Ah, Al, Bh, Bl};
        #pragma unroll
        for (int t = 0; t < 4; t++) {
            const int off = (t < 2) ? m0 : n0;
            const int ld  = (t < 2) ? ldA : ldB;
            gp[t] = (const char*)(bases[t] + (size_t)(off + lrow) * ld);
            #pragma unroll
            for (int j = 0; j < 4; j++) {
                const int seg = sb + j;
                so[t][j] = (uint32_t)(t * TILE_BYTES + lrow * 128 +
                                      ((seg ^ (lrow & 7)) << 4));
            }
        }
    }

    auto load_stage = [&](int slot, int chunk) {
        if (chunk < nchunk) {
            const uint32_t s0 = smem + slot * STAGE_BYTES;
            const size_t goff = (size_t)chunk * 128;    // 64 bf16 = 128 bytes
            #pragma unroll
            for (int t = 0; t < 4; t++) {
                #pragma unroll
                for (int j = 0; j < 4; j++)
                    cp16(s0 + so[t][j], gp[t] + goff + (size_t)(sb + j) * 16);
            }
        }
        cp_commit();
    };

    float acc[2][8][4];
    #pragma unroll
    for (int a = 0; a < 2; a++)
        #pragma unroll
        for (int b = 0; b < 8; b++)
            #pragma unroll
            for (int c = 0; c < 4; c++) acc[a][b][c] = 0.f;

    load_stage(0, 0);
    load_stage(1, 1);
    load_stage(2, 2);

    // fragment address components (constant per thread)
    const int a_r  = lane & 15;
    const int a_kh = lane >> 4;
    const int b_nl = ((lane >> 4) & 1) * 8 + (lane & 7);
    const int b_kh = (lane >> 3) & 1;

    for (int i = 0; i < nchunk; i++) {
        cp_wait2();
        __syncthreads();
        const uint32_t s0 = smem + (i % 3) * STAGE_BYTES;

        #pragma unroll
        for (int kk = 0; kk < 4; kk++) {
            uint32_t ahf[2][4], alf[2][4], bhf[4][4], blf[4][4];
            // A fragments (two m16 tiles, hi+lo)
            #pragma unroll
            for (int mt = 0; mt < 2; mt++) {
                const int row = wm * 32 + mt * 16 + a_r;
                const int seg = kk * 2 + a_kh;
                const uint32_t off = (uint32_t)(row * 128 + ((seg ^ (row & 7)) << 4));
                ldm4(ahf[mt], s0 + 0 * TILE_BYTES + off);
                ldm4(alf[mt], s0 + 1 * TILE_BYTES + off);
            }
            // B fragments (four n16 groups = 8 n8 tiles, hi+lo)
            #pragma unroll
            for (int p = 0; p < 4; p++) {
                const int row = wn * 64 + p * 16 + b_nl;
                const int seg = kk * 2 + b_kh;
                const uint32_t off = (uint32_t)(row * 128 + ((seg ^ (row & 7)) << 4));
                ldm4(bhf[p], s0 + 2 * TILE_BYTES + off);
                ldm4(blf[p], s0 + 3 * TILE_BYTES + off);
            }
            // 3-term MMAs
            #pragma unroll
            for (int mt = 0; mt < 2; mt++) {
                #pragma unroll
                for (int nt = 0; nt < 8; nt++) {
                    const int p = nt >> 1, o = (nt & 1) * 2;
                    mma16816(acc[mt][nt], ahf[mt], &bhf[p][o]);
                    mma16816(acc[mt][nt], ahf[mt], &blf[p][o]);
                    mma16816(acc[mt][nt], alf[mt], &bhf[p][o]);
                }
            }
        }
        __syncthreads();
        load_stage(i % 3, i + 3);
    }

    // ---- epilogue -----------------------------------------------------------
    #pragma unroll
    for (int mt = 0; mt < 2; mt++) {
        #pragma unroll
        for (int h = 0; h < 2; h++) {
            const int row = m0 + wm * 32 + mt * 16 + (lane >> 2) + 8 * h;
            #pragma unroll
            for (int nt = 0; nt < 8; nt++) {
                const int col = n0 + wn * 64 + nt * 8 + (lane & 3) * 2;
                float v0 = acc[mt][nt][2 * h + 0] * scale;
                float v1 = acc[mt][nt][2 * h + 1] * scale;
                if (HAS_BIAS) {
                    const float2 bb = *reinterpret_cast<const float2*>(bias + col);
                    v0 += bb.x; v1 += bb.y;
                }
                if (OUTMODE == 0) {
                    *reinterpret_cast<float2*>(
                        Cf + (size_t)z * sC + (size_t)row * ldC + col) =
                        make_float2(v0, v1);
                } else {
                    float h0 = __bfloat162float(__float2bfloat16(v0));
                    float h1 = __bfloat162float(__float2bfloat16(v1));
                    *reinterpret_cast<uint32_t*>(
                        Ch + (size_t)z * sC + (size_t)row * ldC + col) = pk2(h0, h1);
                    *reinterpret_cast<uint32_t*>(
                        Cl + (size_t)z * sC + (size_t)row * ldC + col) =
                        pk2(v0 - h0, v1 - h1);
                }
            }
        }
    }
}

// ============================================================================
// prep kernels
// ============================================================================
__global__ void split_kernel(const float* __restrict__ in,
                             bf16* __restrict__ oh, bf16* __restrict__ ol, int n)
{
    int i = blockIdx.x * blockDim.x + threadIdx.x;
    if (i >= n) return;
    float v = in[i];
    bf16 h = __float2bfloat16(v);
    oh[i] = h;
    ol[i] = __float2bfloat16(v - __bfloat162float(h));
}

// transpose + split: in [R,C] fp32 -> out hi/lo [C,R] bf16 (batched via z)
__global__ void tsplit_kernel(const float* __restrict__ in,
                              bf16* __restrict__ oh, bf16* __restrict__ ol,
                              int R, int C, size_t sIn, size_t sOut)
{
    __shared__ float t[32][33];
    const int z = blockIdx.z;
    in += (size_t)z * sIn; oh += (size_t)z * sOut; ol += (size_t)z * sOut;
    const int c0 = blockIdx.x * 32, r0 = blockIdx.y * 32;
    const int tx = threadIdx.x, ty = threadIdx.y;
    #pragma unroll
    for (int k = 0; k < 4; k++)
        t[ty + 8 * k][tx] = in[(size_t)(r0 + ty + 8 * k) * C + c0 + tx];
    __syncthreads();
    #pragma unroll
    for (int k = 0; k < 4; k++) {
        float v = t[tx][ty + 8 * k];
        bf16 h = __float2bfloat16(v);
        size_t o = (size_t)(c0 + ty + 8 * k) * R + r0 + tx;
        oh[o] = h;
        ol[o] = __float2bfloat16(v - __bfloat162float(h));
    }
}

// causal softmax: read fp32 scores row [0..q], write split bf16 weights,
// zero-fill tail to the next 128 boundary (covers P@V chunk granularity).
__global__ __launch_bounds__(256)
void softmax_split_kernel(float* __restrict__ P,
                          bf16* __restrict__ Ph, bf16* __restrict__ Pl)
{
    const int rowi = blockIdx.x;
    const int b = rowi / SEQ, q = rowi % SEQ;
    const size_t off = (size_t)b * SEQ * SEQ + (size_t)q * SEQ;
    float* p = P + off;
    bf16* ph = Ph + off;
    bf16* pl = Pl + off;
    const int n = q + 1;

    __shared__ float red[256];
    const int tid = threadIdx.x;

    float mx = -CUDART_INF_F;
    for (int k = tid; k < n; k += 256) mx = fmaxf(mx, p[k]);
    red[tid] = mx; __syncthreads();
    #pragma unroll
    for (int s = 128; s > 0; s >>= 1) {
        if (tid < s) red[tid] = fmaxf(red[tid], red[tid + s]);
        __syncthreads();
    }
    mx = red[0]; __syncthreads();

    float sum = 0.f;
    for (int k = tid; k < n; k += 256) {
        float e = expf(p[k] - mx);
        p[k] = e;
        sum += e;
    }
    red[tid] = sum; __syncthreads();
    #pragma unroll
    for (int s = 128; s > 0; s >>= 1) {
        if (tid < s) red[tid] += red[tid + s];
        __syncthreads();
    }
    const float inv = 1.f / red[0];

    for (int k = tid; k < n; k += 256) {
        float w = p[k] * inv;
        bf16 h = __float2bfloat16(w);
        ph[k] = h;
        pl[k] = __float2bfloat16(w - __bfloat162float(h));
    }
    const int fillEnd = ((q >> 7) + 1) << 7;
    for (int k = n + tid; k < fillEnd; k += 256) {
        ph[k] = __float2bfloat16(0.f);
        pl[k] = __float2bfloat16(0.f);
    }
}

// ============================================================================
extern "C" void kernel_launch(void* const* d_in, const int*, int, void* d_out, int)
{
    const float* x  = (const float*)d_in[0];
    const float* Wq = (const float*)d_in[1];
    const float* bq = (const float*)d_in[2];
    const float* Wk = (const float*)d_in[3];
    const float* bk = (const float*)d_in[4];
    const float* Wv = (const float*)d_in[5];
    const float* bv = (const float*)d_in[6];
    const float* Wo = (const float*)d_in[7];
    const float* bo = (const float*)d_in[8];
    float* out = (float*)d_out;

    bf16 *xh, *xl, *wqh, *wql, *wkh, *wkl, *wvh, *wvl, *woh, *wol;
    bf16 *qh, *ql, *kh, *kl, *vth, *vtl, *phh, *pll, *aoh, *aol;
    float *v, *p;
    cudaGetSymbolAddress((void**)&xh,  g_xh);  cudaGetSymbolAddress((void**)&xl,  g_xl);
    cudaGetSymbolAddress((void**)&wqh, g_wqh); cudaGetSymbolAddress((void**)&wql, g_wql);
    cudaGetSymbolAddress((void**)&wkh, g_wkh); cudaGetSymbolAddress((void**)&wkl, g_wkl);
    cudaGetSymbolAddress((void**)&wvh, g_wvh); cudaGetSymbolAddress((void**)&wvl, g_wvl);
    cudaGetSymbolAddress((void**)&woh, g_woh); cudaGetSymbolAddress((void**)&wol, g_wol);
    cudaGetSymbolAddress((void**)&qh,  g_qh);  cudaGetSymbolAddress((void**)&ql,  g_ql);
    cudaGetSymbolAddress((void**)&kh,  g_kh);  cudaGetSymbolAddress((void**)&kl,  g_kl);
    cudaGetSymbolAddress((void**)&v,   g_v);
    cudaGetSymbolAddress((void**)&vth, g_vth); cudaGetSymbolAddress((void**)&vtl, g_vtl);
    cudaGetSymbolAddress((void**)&p,   g_p);
    cudaGetSymbolAddress((void**)&phh, g_ph);  cudaGetSymbolAddress((void**)&pll, g_pl);
    cudaGetSymbolAddress((void**)&aoh, g_aoh); cudaGetSymbolAddress((void**)&aol, g_aol);

    cudaFuncSetAttribute(tc_gemm<1, true,  false, false>, cudaFuncAttributeMaxDynamicSharedMemorySize, SMEM_DYN);
    cudaFuncSetAttribute(tc_gemm<0, true,  false, false>, cudaFuncAttributeMaxDynamicSharedMemorySize, SMEM_DYN);
    cudaFuncSetAttribute(tc_gemm<0, false, true,  false>, cudaFuncAttributeMaxDynamicSharedMemorySize, SMEM_DYN);
    cudaFuncSetAttribute(tc_gemm<1, false, false, true >, cudaFuncAttributeMaxDynamicSharedMemorySize, SMEM_DYN);

    // ---- prep: split x, transpose+split weights ----------------------------
    split_kernel<<<(MROWS * DM + 255) / 256, 256>>>(x, xh, xl, MROWS * DM);
    {
        dim3 blk(32, 8), grid(DM / 32, DM / 32, 1);
        tsplit_kernel<<<grid, blk>>>(Wq, wqh, wql, DM, DM, 0, 0);
        tsplit_kernel<<<grid, blk>>>(Wk, wkh, wkl, DM, DM, 0, 0);
        tsplit_kernel<<<grid, blk>>>(Wv, wvh, wvl, DM, DM, 0, 0);
        tsplit_kernel<<<grid, blk>>>(Wo, woh, wol, DM, DM, 0, 0);
    }

    // ---- Q, K (split bf16 out) and V (fp32 out) projections ----------------
    {
        dim3 grid(DM / TN, MROWS / TM, 1), blk(256);
        tc_gemm<1, true, false, false><<<grid, blk, SMEM_DYN>>>(
            xh, xl, wqh, wql, bq, nullptr, qh, ql, DM, DM, DM, DM, 1.f, 0, 0, 0);
        tc_gemm<1, true, false, false><<<grid, blk, SMEM_DYN>>>(
            xh, xl, wkh, wkl, bk, nullptr, kh, kl, DM, DM, DM, DM, 1.f, 0, 0, 0);
        tc_gemm<0, true, false, false><<<grid, blk, SMEM_DYN>>>(
            xh, xl, wvh, wvl, bv, v, nullptr, nullptr, DM, DM, DM, DM, 1.f, 0, 0, 0);
    }

    // ---- V transpose+split: [B][S][D] -> [B][D][S] --------------------------
    {
        dim3 blk(32, 8), grid(DM / 32, SEQ / 32, BATCH);
        tsplit_kernel<<<grid, blk>>>(v, vth, vtl, SEQ, DM,
                                     (size_t)SEQ * DM, (size_t)DM * SEQ);
    }

    // ---- scores = Q @ K^T / 8 (causal tile skip, fp32 out) ------------------
    {
        dim3 grid(SEQ / TN, SEQ / TM, BATCH), blk(256);
        tc_gemm<0, false, true, false><<<grid, blk, SMEM_DYN>>>(
            qh, ql, kh, kl, nullptr, p, nullptr, nullptr,
            DM, DM, DM, SEQ, 0.125f,
            (size_t)SEQ * DM, (size_t)SEQ * DM, (size_t)SEQ * SEQ);
    }

    // ---- softmax (split bf16 weights) ----------------------------------------
    softmax_split_kernel<<<MROWS, 256>>>(p, phh, pll);

    // ---- attn_out = P @ V (K-chunks truncated at causal boundary) -----------
    {
        dim3 grid(DM / TN, SEQ / TM, BATCH), blk(256);
        tc_gemm<1, false, false, true><<<grid, blk, SMEM_DYN>>>(
            phh, pll, vth, vtl, nullptr, nullptr, aoh, aol,
            SEQ, SEQ, SEQ, DM, 1.f,
            (size_t)SEQ * SEQ, (size_t)DM * SEQ, (size_t)SEQ * DM);
    }

    // ---- out = attn_out @ Wo + bo (fp32 out) --------------------------------
    {
        dim3 grid(DM / TN, MROWS / TM, 1), blk(256);
        tc_gemm<0, true, false, false><<<grid, blk, SMEM_DYN>>>(
            aoh, aol, woh, wol, bo, out, nullptr, nullptr,
            DM, DM, DM, DM, 1.f, 0, 0, 0);
    }
}